// round 1
// baseline (speedup 1.0000x reference)
#include <cuda_runtime.h>
#include <math.h>

#define DIMV   1024
#define HEADS  16
#define HD     64
#define BATCH  8
#define SEQ    1024
#define MTOT   (BATCH*SEQ)      /* 8192 */
#define SCALEF 0.125f           /* 64^-0.5 */

/* ------------------------------------------------------------------ */
/* scratch (static device globals: allocation-free)                    */
/* ------------------------------------------------------------------ */
__device__ float g_q[BATCH*HEADS*SEQ*HD];
__device__ float g_k[BATCH*HEADS*SEQ*HD];
__device__ float g_v[BATCH*HEADS*SEQ*HD];
__device__ float g_attn[(size_t)MTOT*DIMV];

/* ------------------------------------------------------------------ */
/* NT GEMM: C[M,N] = A[M,K] * B[N,K]^T  (both K-contiguous)            */
/* MODE 0: QKV epilogue -> scatter into g_q/g_k/g_v                    */
/* MODE 1: proj epilogue -> out = acc + bias (A taken from g_attn)     */
/* 128x128 tile, BK=16, 256 threads, 8x8 per-thread microtile          */
/* ------------------------------------------------------------------ */
template<int MODE>
__global__ void __launch_bounds__(256) gemm_nt(
    const float* __restrict__ A, const float* __restrict__ Bm,
    int M, int Nn, int K,
    const float* __restrict__ bias, float* __restrict__ out)
{
    __shared__ float As[16][128];
    __shared__ float Bs[16][128];

    const float* Ap = (MODE == 1) ? g_attn : A;

    int tid = threadIdx.x;
    int tx = tid & 15;
    int ty = tid >> 4;
    int m0 = blockIdx.y * 128;
    int n0 = blockIdx.x * 128;

    float acc[8][8];
#pragma unroll
    for (int i = 0; i < 8; i++)
#pragma unroll
        for (int j = 0; j < 8; j++) acc[i][j] = 0.f;

    for (int k0 = 0; k0 < K; k0 += 16) {
        /* load 128x16 tiles of A and B, store transposed As[k][m] */
#pragma unroll
        for (int i = 0; i < 2; i++) {
            int idx = tid * 2 + i;          /* 0..511 */
            int row = idx >> 2;             /* 0..127 */
            int kq  = (idx & 3) * 4;        /* 0,4,8,12 */
            float4 va = *(const float4*)&Ap[(size_t)(m0 + row) * K + k0 + kq];
            As[kq + 0][row] = va.x; As[kq + 1][row] = va.y;
            As[kq + 2][row] = va.z; As[kq + 3][row] = va.w;
            float4 vb = *(const float4*)&Bm[(size_t)(n0 + row) * K + k0 + kq];
            Bs[kq + 0][row] = vb.x; Bs[kq + 1][row] = vb.y;
            Bs[kq + 2][row] = vb.z; Bs[kq + 3][row] = vb.w;
        }
        __syncthreads();

#pragma unroll
        for (int k = 0; k < 16; k++) {
            float4 a0 = *(const float4*)&As[k][ty * 4];
            float4 a1 = *(const float4*)&As[k][64 + ty * 4];
            float4 b0 = *(const float4*)&Bs[k][tx * 4];
            float4 b1 = *(const float4*)&Bs[k][64 + tx * 4];
            float av[8] = {a0.x, a0.y, a0.z, a0.w, a1.x, a1.y, a1.z, a1.w};
            float bv[8] = {b0.x, b0.y, b0.z, b0.w, b1.x, b1.y, b1.z, b1.w};
#pragma unroll
            for (int i = 0; i < 8; i++)
#pragma unroll
                for (int j = 0; j < 8; j++)
                    acc[i][j] = fmaf(av[i], bv[j], acc[i][j]);
        }
        __syncthreads();
    }

    /* epilogue */
#pragma unroll
    for (int i = 0; i < 8; i++) {
        int row = m0 + ((i < 4) ? (ty * 4 + i) : (64 + ty * 4 + i - 4));
#pragma unroll
        for (int j = 0; j < 8; j++) {
            int col = n0 + ((j < 4) ? (tx * 4 + j) : (64 + tx * 4 + j - 4));
            float v = acc[i][j];
            if (MODE == 0) {
                int qkv = col >> 10;           /* 0,1,2 */
                int h   = (col >> 6) & 15;
                int dd  = col & 63;
                int b   = row >> 10;
                int n   = row & 1023;
                size_t off = ((((size_t)b * HEADS + h) * SEQ) + n) * HD + dd;
                float* dst = (qkv == 0) ? g_q : ((qkv == 1) ? g_k : g_v);
                dst[off] = v;
            } else {
                out[(size_t)row * Nn + col] = v + bias[col];
            }
        }
    }
}

/* ------------------------------------------------------------------ */
/* Flash attention: grid (16 qtiles, 128 bh), 256 threads (16x16)      */
/* BM=BN=64, d=64. 4x4 microtiles for S and O. Online softmax.         */
/* Dynamic shared: Qs/Ks (transposed [d][m]), Vs [n][d], Ps [n][m],    */
/* all padded to stride 68 (16B-aligned, bank-shifted).                */
/* ------------------------------------------------------------------ */
#define PADW 68

__global__ void __launch_bounds__(256) attn_kernel()
{
    extern __shared__ float sm[];
    float* Qs = sm;                 /* [64][PADW]  Qs[d][m]   */
    float* Ks = Qs + 64 * PADW;     /* [64][PADW]  Ks[d][n]   */
    float* Vs = Ks + 64 * PADW;     /* [64][PADW]  Vs[n][d]   */
    float* Ps = Vs + 64 * PADW;     /* [64][PADW]  Ps[n][m]   */

    int tid = threadIdx.x;
    int tx = tid & 15;
    int ty = tid >> 4;
    int bh = blockIdx.y;            /* b*16 + h */
    int m0 = blockIdx.x * 64;

    const float* qptr = g_q + (size_t)bh * SEQ * HD;
    const float* kptr = g_k + (size_t)bh * SEQ * HD;
    const float* vptr = g_v + (size_t)bh * SEQ * HD;

    /* load Q tile transposed */
#pragma unroll
    for (int i = 0; i < 4; i++) {
        int idx = tid * 4 + i;       /* 0..1023 */
        int row = idx >> 4;          /* 0..63   */
        int dq  = (idx & 15) * 4;
        float4 v4 = *(const float4*)&qptr[(size_t)(m0 + row) * HD + dq];
        Qs[(dq + 0) * PADW + row] = v4.x; Qs[(dq + 1) * PADW + row] = v4.y;
        Qs[(dq + 2) * PADW + row] = v4.z; Qs[(dq + 3) * PADW + row] = v4.w;
    }

    float o[4][4];
    float mrow[4], lrow[4];
#pragma unroll
    for (int i = 0; i < 4; i++) {
        mrow[i] = -1e30f; lrow[i] = 0.f;
#pragma unroll
        for (int j = 0; j < 4; j++) o[i][j] = 0.f;
    }

    for (int j0 = 0; j0 < SEQ; j0 += 64) {
        __syncthreads();   /* protect Ks/Vs/Ps from previous iteration; also Qs on iter 0 */

        /* load K (transposed) and V (natural) tiles */
#pragma unroll
        for (int i = 0; i < 4; i++) {
            int idx = tid * 4 + i;
            int row = idx >> 4;
            int dq  = (idx & 15) * 4;
            float4 kv = *(const float4*)&kptr[(size_t)(j0 + row) * HD + dq];
            Ks[(dq + 0) * PADW + row] = kv.x; Ks[(dq + 1) * PADW + row] = kv.y;
            Ks[(dq + 2) * PADW + row] = kv.z; Ks[(dq + 3) * PADW + row] = kv.w;
            float4 vv = *(const float4*)&vptr[(size_t)(j0 + row) * HD + dq];
            *(float4*)&Vs[row * PADW + dq] = vv;
        }
        __syncthreads();

        /* S = Q K^T  (4x4 microtile per thread) */
        float s[4][4];
#pragma unroll
        for (int i = 0; i < 4; i++)
#pragma unroll
            for (int j = 0; j < 4; j++) s[i][j] = 0.f;

#pragma unroll 8
        for (int d = 0; d < 64; d++) {
            float4 qa = *(const float4*)&Qs[d * PADW + ty * 4];
            float4 ka = *(const float4*)&Ks[d * PADW + tx * 4];
            float qv[4] = {qa.x, qa.y, qa.z, qa.w};
            float kv[4] = {ka.x, ka.y, ka.z, ka.w};
#pragma unroll
            for (int i = 0; i < 4; i++)
#pragma unroll
                for (int j = 0; j < 4; j++)
                    s[i][j] = fmaf(qv[i], kv[j], s[i][j]);
        }

        /* online softmax (rows of this thread: ty*4+i; reduce over 16 tx lanes) */
#pragma unroll
        for (int i = 0; i < 4; i++) {
#pragma unroll
            for (int j = 0; j < 4; j++) s[i][j] *= SCALEF;
            float tm = fmaxf(fmaxf(s[i][0], s[i][1]), fmaxf(s[i][2], s[i][3]));
#pragma unroll
            for (int off = 1; off < 16; off <<= 1)
                tm = fmaxf(tm, __shfl_xor_sync(0xffffffffu, tm, off));
            float mnew = fmaxf(mrow[i], tm);
            float alpha = __expf(mrow[i] - mnew);
            mrow[i] = mnew;
            float lsum = 0.f;
#pragma unroll
            for (int j = 0; j < 4; j++) {
                s[i][j] = __expf(s[i][j] - mnew);
                lsum += s[i][j];
            }
#pragma unroll
            for (int off = 1; off < 16; off <<= 1)
                lsum += __shfl_xor_sync(0xffffffffu, lsum, off);
            lrow[i] = lrow[i] * alpha + lsum;
#pragma unroll
            for (int j = 0; j < 4; j++) o[i][j] *= alpha;
        }

        /* write P transposed: Ps[key][qrow] */
#pragma unroll
        for (int i = 0; i < 4; i++)
#pragma unroll
            for (int j = 0; j < 4; j++)
                Ps[(tx * 4 + j) * PADW + ty * 4 + i] = s[i][j];
        __syncthreads();

        /* O += P V */
#pragma unroll 8
        for (int jj = 0; jj < 64; jj++) {
            float4 pa = *(const float4*)&Ps[jj * PADW + ty * 4];
            float4 va = *(const float4*)&Vs[jj * PADW + tx * 4];
            float pv[4] = {pa.x, pa.y, pa.z, pa.w};
            float vv[4] = {va.x, va.y, va.z, va.w};
#pragma unroll
            for (int i = 0; i < 4; i++)
#pragma unroll
                for (int j = 0; j < 4; j++)
                    o[i][j] = fmaf(pv[i], vv[j], o[i][j]);
        }
    }

    /* epilogue: normalize, write [b, n, h*64+d] */
    int b = bh >> 4;
    int h = bh & 15;
#pragma unroll
    for (int i = 0; i < 4; i++) {
        float inv = 1.f / lrow[i];
        size_t rowbase = ((size_t)(b * SEQ + m0 + ty * 4 + i)) * DIMV + h * HD + tx * 4;
#pragma unroll
        for (int j = 0; j < 4; j++)
            g_attn[rowbase + j] = o[i][j] * inv;
    }
}

/* ------------------------------------------------------------------ */
extern "C" void kernel_launch(void* const* d_in, const int* in_sizes, int n_in,
                              void* d_out, int out_size)
{
    /* identify inputs by element count (all distinct) */
    const float* x = nullptr;      /* 8*1024*1024  = 8388608 */
    const float* Wqkv = nullptr;   /* 3072*1024    = 3145728 */
    const float* Wproj = nullptr;  /* 1024*1024    = 1048576 */
    const float* bproj = nullptr;  /* 1024                   */
    for (int i = 0; i < n_in; i++) {
        switch (in_sizes[i]) {
            case 8388608: x     = (const float*)d_in[i]; break;
            case 3145728: Wqkv  = (const float*)d_in[i]; break;
            case 1048576: Wproj = (const float*)d_in[i]; break;
            case 1024:    bproj = (const float*)d_in[i]; break;
            default: break;
        }
    }
    float* out = (float*)d_out;

    /* QKV GEMM: [8192,1024] x [3072,1024]^T */
    {
        dim3 grid(3 * DIMV / 128, MTOT / 128);   /* 24 x 64 */
        gemm_nt<0><<<grid, 256>>>(x, Wqkv, MTOT, 3 * DIMV, DIMV, nullptr, nullptr);
    }

    /* attention */
    {
        size_t smem = 4 * 64 * PADW * sizeof(float);   /* 69632 B */
        cudaFuncSetAttribute(attn_kernel,
                             cudaFuncAttributeMaxDynamicSharedMemorySize,
                             (int)smem);
        dim3 grid(SEQ / 64, BATCH * HEADS);      /* 16 x 128 */
        attn_kernel<<<grid, 256, smem>>>();
    }

    /* projection GEMM + bias: [8192,1024] x [1024,1024]^T + b */
    {
        dim3 grid(DIMV / 128, MTOT / 128);       /* 8 x 64 */
        gemm_nt<1><<<grid, 256>>>(nullptr, Wproj, MTOT, DIMV, DIMV, bproj, out);
    }
    (void)out_size; (void)n_in;
}

// round 3
// speedup vs baseline: 1.7130x; 1.7130x over previous
#include <cuda_runtime.h>
#include <cuda_bf16.h>
#include <math.h>
#include <stdint.h>

#define DIMV   1024
#define HEADS  16
#define HD     64
#define BATCH  8
#define SEQ    1024
#define MTOT   (BATCH*SEQ)      /* 8192 */
#define SCALEF 0.125f

/* ------------------------------------------------------------------ */
__device__ float g_q[BATCH*HEADS*SEQ*HD];
__device__ float g_k[BATCH*HEADS*SEQ*HD];
__device__ float g_v[BATCH*HEADS*SEQ*HD];
__device__ float g_attn[(size_t)MTOT*DIMV];

__device__ __forceinline__ uint32_t smem_u32(const void* p) {
    uint32_t a;
    asm("{ .reg .u64 t; cvta.to.shared.u64 t, %1; cvt.u32.u64 %0, t; }"
        : "=r"(a) : "l"(p));
    return a;
}
__device__ __forceinline__ void ldm_x4(uint32_t* r, uint32_t addr) {
    asm volatile("ldmatrix.sync.aligned.m8n8.x4.shared.b16 {%0,%1,%2,%3}, [%4];"
                 : "=r"(r[0]), "=r"(r[1]), "=r"(r[2]), "=r"(r[3]) : "r"(addr));
}
__device__ __forceinline__ void mma_bf16(float* c, const uint32_t* a, const uint32_t* b) {
    asm volatile("mma.sync.aligned.m16n8k16.row.col.f32.bf16.bf16.f32 "
                 "{%0,%1,%2,%3}, {%4,%5,%6,%7}, {%8,%9}, {%0,%1,%2,%3};"
                 : "+f"(c[0]), "+f"(c[1]), "+f"(c[2]), "+f"(c[3])
                 : "r"(a[0]), "r"(a[1]), "r"(a[2]), "r"(a[3]), "r"(b[0]), "r"(b[1]));
}

/* ------------------------------------------------------------------ */
/* mma.sync GEMM: C[M,N] = A[M,K]*B[N,K]^T, fp32 via bf16 hi/lo split  */
/* BM=BN=128, BK=32, 8 warps (2x4), warp tile 64x32, smem stride 40.   */
/* MODE 0: QKV scatter -> g_q/g_k/g_v.  MODE 1: out = acc + bias.      */
/* ------------------------------------------------------------------ */
#define SP 40   /* bf16 elems per smem row (80 B) */

template<int MODE>
__global__ void __launch_bounds__(256, 2) gemm_mma(
    const float* __restrict__ A, const float* __restrict__ Bw,
    int Nn, const float* __restrict__ bias, float* __restrict__ out)
{
    __shared__ __nv_bfloat16 sAh[128 * SP];
    __shared__ __nv_bfloat16 sAl[128 * SP];
    __shared__ __nv_bfloat16 sBh[128 * SP];
    __shared__ __nv_bfloat16 sBl[128 * SP];

    const float* Ap = (MODE == 1) ? g_attn : A;
    const int tid  = threadIdx.x;
    const int lane = tid & 31;
    const int wid  = tid >> 5;
    const int wm   = wid >> 2;          /* 0..1 */
    const int wn   = wid & 3;           /* 0..3 */
    const int m0   = blockIdx.y * 128;
    const int n0   = blockIdx.x * 128;

    const uint32_t uAh = smem_u32(sAh);
    const uint32_t uAl = smem_u32(sAl);
    const uint32_t uBh = smem_u32(sBh);
    const uint32_t uBl = smem_u32(sBl);

    /* ldmatrix per-lane row/col offsets */
    const int a_lrow = (lane & 7) + ((lane >> 3) & 1) * 8;   /* A: rows  */
    const int a_lkof = (lane >> 4) * 8;                      /* A: k off */
    const int b_lrow = (lane & 7) + (lane >> 4) * 8;         /* B: n rows*/
    const int b_lkof = ((lane >> 3) & 1) * 8;                /* B: k off */

    float acc[4][4][4];
#pragma unroll
    for (int i = 0; i < 4; i++)
#pragma unroll
        for (int j = 0; j < 4; j++)
#pragma unroll
            for (int r = 0; r < 4; r++) acc[i][j][r] = 0.f;

    const int row_l = tid >> 3;        /* 0..31 step over 128 rows via t */
    const int cq    = tid & 7;         /* float4 col 0..7 (32 cols)      */

    for (int k0 = 0; k0 < DIMV; k0 += 32) {
        /* ---- load 128x32 fp32 of A and B, split to bf16 hi/lo ---- */
#pragma unroll
        for (int t = 0; t < 4; t++) {
            int row = row_l + t * 32;
            uint32_t so = (uint32_t)(row * SP + cq * 4) * 2;

            float4 a = *(const float4*)&Ap[(size_t)(m0 + row) * DIMV + k0 + cq * 4];
            __nv_bfloat162 h01 = __floats2bfloat162_rn(a.x, a.y);
            __nv_bfloat162 h23 = __floats2bfloat162_rn(a.z, a.w);
            __nv_bfloat162 l01 = __floats2bfloat162_rn(a.x - __bfloat162float(h01.x),
                                                       a.y - __bfloat162float(h01.y));
            __nv_bfloat162 l23 = __floats2bfloat162_rn(a.z - __bfloat162float(h23.x),
                                                       a.w - __bfloat162float(h23.y));
            asm volatile("st.shared.v2.u32 [%0], {%1,%2};" ::
                "r"(uAh + so), "r"(*(uint32_t*)&h01), "r"(*(uint32_t*)&h23));
            asm volatile("st.shared.v2.u32 [%0], {%1,%2};" ::
                "r"(uAl + so), "r"(*(uint32_t*)&l01), "r"(*(uint32_t*)&l23));

            float4 b = *(const float4*)&Bw[(size_t)(n0 + row) * DIMV + k0 + cq * 4];
            __nv_bfloat162 bh01 = __floats2bfloat162_rn(b.x, b.y);
            __nv_bfloat162 bh23 = __floats2bfloat162_rn(b.z, b.w);
            __nv_bfloat162 bl01 = __floats2bfloat162_rn(b.x - __bfloat162float(bh01.x),
                                                        b.y - __bfloat162float(bh01.y));
            __nv_bfloat162 bl23 = __floats2bfloat162_rn(b.z - __bfloat162float(bh23.x),
                                                        b.w - __bfloat162float(bh23.y));
            asm volatile("st.shared.v2.u32 [%0], {%1,%2};" ::
                "r"(uBh + so), "r"(*(uint32_t*)&bh01), "r"(*(uint32_t*)&bh23));
            asm volatile("st.shared.v2.u32 [%0], {%1,%2};" ::
                "r"(uBl + so), "r"(*(uint32_t*)&bl01), "r"(*(uint32_t*)&bl23));
        }
        __syncthreads();

        /* ---- compute: 2 k-steps of 16 ---- */
#pragma unroll
        for (int ks = 0; ks < 2; ks++) {
            const int kk = ks * 16;

            uint32_t bfh[2][4], bfl[2][4];
#pragma unroll
            for (int bi = 0; bi < 2; bi++) {
                uint32_t boff = (uint32_t)((wn * 32 + bi * 16 + b_lrow) * SP
                                           + kk + b_lkof) * 2;
                ldm_x4(bfh[bi], uBh + boff);
                ldm_x4(bfl[bi], uBl + boff);
            }
#pragma unroll
            for (int mi = 0; mi < 4; mi++) {
                uint32_t af_h[4], af_l[4];
                uint32_t aoff = (uint32_t)((wm * 64 + mi * 16 + a_lrow) * SP
                                           + kk + a_lkof) * 2;
                ldm_x4(af_h, uAh + aoff);
                ldm_x4(af_l, uAl + aoff);
#pragma unroll
                for (int ni = 0; ni < 4; ni++) {
                    const uint32_t* bh = &bfh[ni >> 1][(ni & 1) * 2];
                    const uint32_t* bl = &bfl[ni >> 1][(ni & 1) * 2];
                    mma_bf16(acc[mi][ni], af_h, bh);
                    mma_bf16(acc[mi][ni], af_h, bl);
                    mma_bf16(acc[mi][ni], af_l, bh);
                }
            }
        }
        __syncthreads();
    }

    /* ---- epilogue ---- */
    const int r_base = wm * 64 + (lane >> 2);
    const int c_base = wn * 32 + (lane & 3) * 2;
#pragma unroll
    for (int mi = 0; mi < 4; mi++) {
#pragma unroll
        for (int ni = 0; ni < 4; ni++) {
            int gcol = n0 + c_base + ni * 8;
#pragma unroll
            for (int half = 0; half < 2; half++) {
                int grow = m0 + r_base + mi * 16 + half * 8;
                float v0 = acc[mi][ni][half * 2 + 0];
                float v1 = acc[mi][ni][half * 2 + 1];
                if (MODE == 0) {
                    int qkv = gcol >> 10;
                    int hh  = (gcol >> 6) & 15;
                    int dd  = gcol & 63;
                    int b   = grow >> 10;
                    int sp  = grow & 1023;
                    float* dst = (qkv == 0 ? g_q : (qkv == 1 ? g_k : g_v))
                                 + (((size_t)(b * HEADS + hh) * SEQ) + sp) * HD + dd;
                    *(float2*)dst = make_float2(v0, v1);
                } else {
                    float2 bb = *(const float2*)&bias[gcol];
                    *(float2*)&out[(size_t)grow * Nn + gcol] =
                        make_float2(v0 + bb.x, v1 + bb.y);
                }
            }
        }
    }
}

/* ------------------------------------------------------------------ */
/* Flash attention (SIMT fp32, proven in round 1)                      */
/* ------------------------------------------------------------------ */
#define PADW 68

__global__ void __launch_bounds__(256) attn_kernel()
{
    extern __shared__ float sm[];
    float* Qs = sm;
    float* Ks = Qs + 64 * PADW;
    float* Vs = Ks + 64 * PADW;
    float* Ps = Vs + 64 * PADW;

    int tid = threadIdx.x;
    int tx = tid & 15;
    int ty = tid >> 4;
    int bh = blockIdx.y;
    int m0 = blockIdx.x * 64;

    const float* qptr = g_q + (size_t)bh * SEQ * HD;
    const float* kptr = g_k + (size_t)bh * SEQ * HD;
    const float* vptr = g_v + (size_t)bh * SEQ * HD;

#pragma unroll
    for (int i = 0; i < 4; i++) {
        int idx = tid * 4 + i;
        int row = idx >> 4;
        int dq  = (idx & 15) * 4;
        float4 v4 = *(const float4*)&qptr[(size_t)(m0 + row) * HD + dq];
        Qs[(dq + 0) * PADW + row] = v4.x; Qs[(dq + 1) * PADW + row] = v4.y;
        Qs[(dq + 2) * PADW + row] = v4.z; Qs[(dq + 3) * PADW + row] = v4.w;
    }

    float o[4][4];
    float mrow[4], lrow[4];
#pragma unroll
    for (int i = 0; i < 4; i++) {
        mrow[i] = -1e30f; lrow[i] = 0.f;
#pragma unroll
        for (int j = 0; j < 4; j++) o[i][j] = 0.f;
    }

    for (int j0 = 0; j0 < SEQ; j0 += 64) {
        __syncthreads();
#pragma unroll
        for (int i = 0; i < 4; i++) {
            int idx = tid * 4 + i;
            int row = idx >> 4;
            int dq  = (idx & 15) * 4;
            float4 kv = *(const float4*)&kptr[(size_t)(j0 + row) * HD + dq];
            Ks[(dq + 0) * PADW + row] = kv.x; Ks[(dq + 1) * PADW + row] = kv.y;
            Ks[(dq + 2) * PADW + row] = kv.z; Ks[(dq + 3) * PADW + row] = kv.w;
            float4 vv = *(const float4*)&vptr[(size_t)(j0 + row) * HD + dq];
            *(float4*)&Vs[row * PADW + dq] = vv;
        }
        __syncthreads();

        float s[4][4];
#pragma unroll
        for (int i = 0; i < 4; i++)
#pragma unroll
            for (int j = 0; j < 4; j++) s[i][j] = 0.f;

#pragma unroll 8
        for (int d = 0; d < 64; d++) {
            float4 qa = *(const float4*)&Qs[d * PADW + ty * 4];
            float4 ka = *(const float4*)&Ks[d * PADW + tx * 4];
            float qv[4] = {qa.x, qa.y, qa.z, qa.w};
            float kv[4] = {ka.x, ka.y, ka.z, ka.w};
#pragma unroll
            for (int i = 0; i < 4; i++)
#pragma unroll
                for (int j = 0; j < 4; j++)
                    s[i][j] = fmaf(qv[i], kv[j], s[i][j]);
        }

#pragma unroll
        for (int i = 0; i < 4; i++) {
#pragma unroll
            for (int j = 0; j < 4; j++) s[i][j] *= SCALEF;
            float tm = fmaxf(fmaxf(s[i][0], s[i][1]), fmaxf(s[i][2], s[i][3]));
#pragma unroll
            for (int off = 1; off < 16; off <<= 1)
                tm = fmaxf(tm, __shfl_xor_sync(0xffffffffu, tm, off));
            float mnew = fmaxf(mrow[i], tm);
            float alpha = __expf(mrow[i] - mnew);
            mrow[i] = mnew;
            float lsum = 0.f;
#pragma unroll
            for (int j = 0; j < 4; j++) {
                s[i][j] = __expf(s[i][j] - mnew);
                lsum += s[i][j];
            }
#pragma unroll
            for (int off = 1; off < 16; off <<= 1)
                lsum += __shfl_xor_sync(0xffffffffu, lsum, off);
            lrow[i] = lrow[i] * alpha + lsum;
#pragma unroll
            for (int j = 0; j < 4; j++) o[i][j] *= alpha;
        }

#pragma unroll
        for (int i = 0; i < 4; i++)
#pragma unroll
            for (int j = 0; j < 4; j++)
                Ps[(tx * 4 + j) * PADW + ty * 4 + i] = s[i][j];
        __syncthreads();

#pragma unroll 8
        for (int jj = 0; jj < 64; jj++) {
            float4 pa = *(const float4*)&Ps[jj * PADW + ty * 4];
            float4 va = *(const float4*)&Vs[jj * PADW + tx * 4];
            float pv[4] = {pa.x, pa.y, pa.z, pa.w};
            float vv[4] = {va.x, va.y, va.z, va.w};
#pragma unroll
            for (int i = 0; i < 4; i++)
#pragma unroll
                for (int j = 0; j < 4; j++)
                    o[i][j] = fmaf(pv[i], vv[j], o[i][j]);
        }
    }

    int b = bh >> 4;
    int h = bh & 15;
#pragma unroll
    for (int i = 0; i < 4; i++) {
        float inv = 1.f / lrow[i];
        size_t rowbase = ((size_t)(b * SEQ + m0 + ty * 4 + i)) * DIMV + h * HD + tx * 4;
#pragma unroll
        for (int j = 0; j < 4; j++)
            g_attn[rowbase + j] = o[i][j] * inv;
    }
}

/* ------------------------------------------------------------------ */
extern "C" void kernel_launch(void* const* d_in, const int* in_sizes, int n_in,
                              void* d_out, int out_size)
{
    const float* x = nullptr;      /* 8388608 */
    const float* Wqkv = nullptr;   /* 3145728 */
    const float* Wproj = nullptr;  /* 1048576 */
    const float* bproj = nullptr;  /* 1024    */
    for (int i = 0; i < n_in; i++) {
        switch (in_sizes[i]) {
            case 8388608: x     = (const float*)d_in[i]; break;
            case 3145728: Wqkv  = (const float*)d_in[i]; break;
            case 1048576: Wproj = (const float*)d_in[i]; break;
            case 1024:    bproj = (const float*)d_in[i]; break;
            default: break;
        }
    }
    float* out = (float*)d_out;

    /* QKV GEMM (mma.sync bf16 hi/lo) */
    {
        dim3 grid(3 * DIMV / 128, MTOT / 128);   /* 24 x 64 */
        gemm_mma<0><<<grid, 256>>>(x, Wqkv, 3 * DIMV, nullptr, nullptr);
    }

    /* attention (SIMT fp32) */
    {
        size_t smem = 4 * 64 * PADW * sizeof(float);
        cudaFuncSetAttribute(attn_kernel, cudaFuncAttributeMaxDynamicSharedMemorySize,
                             (int)smem);
        dim3 grid(SEQ / 64, BATCH * HEADS);      /* 16 x 128 */
        attn_kernel<<<grid, 256, smem>>>();
    }

    /* projection GEMM + bias */
    {
        dim3 grid(DIMV / 128, MTOT / 128);       /* 8 x 64 */
        gemm_mma<1><<<grid, 256>>>(nullptr, Wproj, DIMV, bproj, out);
    }
    (void)out_size; (void)n_in;
}

// round 4
// speedup vs baseline: 3.1894x; 1.8618x over previous
#include <cuda_runtime.h>
#include <cuda_bf16.h>
#include <math.h>
#include <stdint.h>

#define DIMV   1024
#define HEADS  16
#define HD     64
#define BATCH  8
#define SEQ    1024
#define MTOT   (BATCH*SEQ)      /* 8192 */
#define SCALEF 0.125f

/* ------------------------------------------------------------------ */
/* scratch: bf16 hi/lo planes for q,k,v + fp32 attention output        */
/* ------------------------------------------------------------------ */
#define PLANE (BATCH*HEADS*SEQ*HD)
__device__ __nv_bfloat16 g_qh[PLANE], g_ql[PLANE];
__device__ __nv_bfloat16 g_kh[PLANE], g_kl[PLANE];
__device__ __nv_bfloat16 g_vh[PLANE], g_vl[PLANE];
__device__ float g_attn[(size_t)MTOT*DIMV];

__device__ __forceinline__ uint32_t smem_u32(const void* p) {
    uint32_t a;
    asm("{ .reg .u64 t; cvta.to.shared.u64 t, %1; cvt.u32.u64 %0, t; }"
        : "=r"(a) : "l"(p));
    return a;
}
__device__ __forceinline__ void ldm_x4(uint32_t* r, uint32_t addr) {
    asm volatile("ldmatrix.sync.aligned.m8n8.x4.shared.b16 {%0,%1,%2,%3}, [%4];"
                 : "=r"(r[0]), "=r"(r[1]), "=r"(r[2]), "=r"(r[3]) : "r"(addr));
}
__device__ __forceinline__ void ldm_x4_t(uint32_t* r, uint32_t addr) {
    asm volatile("ldmatrix.sync.aligned.m8n8.x4.trans.shared.b16 {%0,%1,%2,%3}, [%4];"
                 : "=r"(r[0]), "=r"(r[1]), "=r"(r[2]), "=r"(r[3]) : "r"(addr));
}
__device__ __forceinline__ void mma_bf16(float* c, const uint32_t* a, const uint32_t* b) {
    asm volatile("mma.sync.aligned.m16n8k16.row.col.f32.bf16.bf16.f32 "
                 "{%0,%1,%2,%3}, {%4,%5,%6,%7}, {%8,%9}, {%0,%1,%2,%3};"
                 : "+f"(c[0]), "+f"(c[1]), "+f"(c[2]), "+f"(c[3])
                 : "r"(a[0]), "r"(a[1]), "r"(a[2]), "r"(a[3]), "r"(b[0]), "r"(b[1]));
}

/* ------------------------------------------------------------------ */
/* mma.sync GEMM (round-3 proven): C = A*B^T, bf16 hi/lo split         */
/* MODE 0: QKV -> bf16 hi/lo planes (Q pre-scaled). MODE 1: +bias out. */
/* ------------------------------------------------------------------ */
#define SP 40

template<int MODE>
__global__ void __launch_bounds__(256, 2) gemm_mma(
    const float* __restrict__ A, const float* __restrict__ Bw,
    int Nn, const float* __restrict__ bias, float* __restrict__ out)
{
    __shared__ __nv_bfloat16 sAh[128 * SP];
    __shared__ __nv_bfloat16 sAl[128 * SP];
    __shared__ __nv_bfloat16 sBh[128 * SP];
    __shared__ __nv_bfloat16 sBl[128 * SP];

    const float* Ap = (MODE == 1) ? g_attn : A;
    const int tid  = threadIdx.x;
    const int lane = tid & 31;
    const int wid  = tid >> 5;
    const int wm   = wid >> 2;
    const int wn   = wid & 3;
    const int m0   = blockIdx.y * 128;
    const int n0   = blockIdx.x * 128;

    const uint32_t uAh = smem_u32(sAh);
    const uint32_t uAl = smem_u32(sAl);
    const uint32_t uBh = smem_u32(sBh);
    const uint32_t uBl = smem_u32(sBl);

    const int a_lrow = (lane & 7) + ((lane >> 3) & 1) * 8;
    const int a_lkof = (lane >> 4) * 8;
    const int b_lrow = (lane & 7) + (lane >> 4) * 8;
    const int b_lkof = ((lane >> 3) & 1) * 8;

    float acc[4][4][4];
#pragma unroll
    for (int i = 0; i < 4; i++)
#pragma unroll
        for (int j = 0; j < 4; j++)
#pragma unroll
            for (int r = 0; r < 4; r++) acc[i][j][r] = 0.f;

    const int row_l = tid >> 3;
    const int cq    = tid & 7;

    for (int k0 = 0; k0 < DIMV; k0 += 32) {
#pragma unroll
        for (int t = 0; t < 4; t++) {
            int row = row_l + t * 32;
            uint32_t so = (uint32_t)(row * SP + cq * 4) * 2;

            float4 a = *(const float4*)&Ap[(size_t)(m0 + row) * DIMV + k0 + cq * 4];
            __nv_bfloat162 h01 = __floats2bfloat162_rn(a.x, a.y);
            __nv_bfloat162 h23 = __floats2bfloat162_rn(a.z, a.w);
            __nv_bfloat162 l01 = __floats2bfloat162_rn(a.x - __bfloat162float(h01.x),
                                                       a.y - __bfloat162float(h01.y));
            __nv_bfloat162 l23 = __floats2bfloat162_rn(a.z - __bfloat162float(h23.x),
                                                       a.w - __bfloat162float(h23.y));
            asm volatile("st.shared.v2.u32 [%0], {%1,%2};" ::
                "r"(uAh + so), "r"(*(uint32_t*)&h01), "r"(*(uint32_t*)&h23));
            asm volatile("st.shared.v2.u32 [%0], {%1,%2};" ::
                "r"(uAl + so), "r"(*(uint32_t*)&l01), "r"(*(uint32_t*)&l23));

            float4 b = *(const float4*)&Bw[(size_t)(n0 + row) * DIMV + k0 + cq * 4];
            __nv_bfloat162 bh01 = __floats2bfloat162_rn(b.x, b.y);
            __nv_bfloat162 bh23 = __floats2bfloat162_rn(b.z, b.w);
            __nv_bfloat162 bl01 = __floats2bfloat162_rn(b.x - __bfloat162float(bh01.x),
                                                        b.y - __bfloat162float(bh01.y));
            __nv_bfloat162 bl23 = __floats2bfloat162_rn(b.z - __bfloat162float(bh23.x),
                                                        b.w - __bfloat162float(bh23.y));
            asm volatile("st.shared.v2.u32 [%0], {%1,%2};" ::
                "r"(uBh + so), "r"(*(uint32_t*)&bh01), "r"(*(uint32_t*)&bh23));
            asm volatile("st.shared.v2.u32 [%0], {%1,%2};" ::
                "r"(uBl + so), "r"(*(uint32_t*)&bl01), "r"(*(uint32_t*)&bl23));
        }
        __syncthreads();

#pragma unroll
        for (int ks = 0; ks < 2; ks++) {
            const int kk = ks * 16;
            uint32_t bfh[2][4], bfl[2][4];
#pragma unroll
            for (int bi = 0; bi < 2; bi++) {
                uint32_t boff = (uint32_t)((wn * 32 + bi * 16 + b_lrow) * SP
                                           + kk + b_lkof) * 2;
                ldm_x4(bfh[bi], uBh + boff);
                ldm_x4(bfl[bi], uBl + boff);
            }
#pragma unroll
            for (int mi = 0; mi < 4; mi++) {
                uint32_t af_h[4], af_l[4];
                uint32_t aoff = (uint32_t)((wm * 64 + mi * 16 + a_lrow) * SP
                                           + kk + a_lkof) * 2;
                ldm_x4(af_h, uAh + aoff);
                ldm_x4(af_l, uAl + aoff);
#pragma unroll
                for (int ni = 0; ni < 4; ni++) {
                    const uint32_t* bh = &bfh[ni >> 1][(ni & 1) * 2];
                    const uint32_t* bl = &bfl[ni >> 1][(ni & 1) * 2];
                    mma_bf16(acc[mi][ni], af_h, bh);
                    mma_bf16(acc[mi][ni], af_h, bl);
                    mma_bf16(acc[mi][ni], af_l, bh);
                }
            }
        }
        __syncthreads();
    }

    const int r_base = wm * 64 + (lane >> 2);
    const int c_base = wn * 32 + (lane & 3) * 2;
#pragma unroll
    for (int mi = 0; mi < 4; mi++) {
#pragma unroll
        for (int ni = 0; ni < 4; ni++) {
            int gcol = n0 + c_base + ni * 8;
#pragma unroll
            for (int half = 0; half < 2; half++) {
                int grow = m0 + r_base + mi * 16 + half * 8;
                float v0 = acc[mi][ni][half * 2 + 0];
                float v1 = acc[mi][ni][half * 2 + 1];
                if (MODE == 0) {
                    int qkv = gcol >> 10;
                    int hh  = (gcol >> 6) & 15;
                    int dd  = gcol & 63;
                    int b   = grow >> 10;
                    int sp  = grow & 1023;
                    size_t off = (((size_t)(b * HEADS + hh) * SEQ) + sp) * HD + dd;
                    if (qkv == 0) { v0 *= SCALEF; v1 *= SCALEF; }
                    __nv_bfloat16 h0 = __float2bfloat16_rn(v0);
                    __nv_bfloat16 h1 = __float2bfloat16_rn(v1);
                    __nv_bfloat16 l0 = __float2bfloat16_rn(v0 - __bfloat162float(h0));
                    __nv_bfloat16 l1 = __float2bfloat16_rn(v1 - __bfloat162float(h1));
                    __nv_bfloat16* ph = (qkv == 0) ? g_qh : (qkv == 1) ? g_kh : g_vh;
                    __nv_bfloat16* pl = (qkv == 0) ? g_ql : (qkv == 1) ? g_kl : g_vl;
                    *(__nv_bfloat162*)&ph[off] = __halves2bfloat162(h0, h1);
                    *(__nv_bfloat162*)&pl[off] = __halves2bfloat162(l0, l1);
                } else {
                    float2 bb = *(const float2*)&bias[gcol];
                    *(float2*)&out[(size_t)grow * Nn + gcol] =
                        make_float2(v0 + bb.x, v1 + bb.y);
                }
            }
        }
    }
}

/* ------------------------------------------------------------------ */
/* Tensor-core flash attention: CTA = (bh, 128 q rows), 8 warps x 16.  */
/* Key chunks of 64. bf16 hi/lo: S = qh*kh+qh*kl+ql*kh; O = ph*vh+...  */
/* P kept in registers (S frag layout == A frag layout).               */
/* ------------------------------------------------------------------ */
#define QP 72   /* smem row stride in bf16 elems (144 B) */

__global__ void __launch_bounds__(256) attn_mma()
{
    extern __shared__ __nv_bfloat16 smb[];
    __nv_bfloat16* Qh = smb;
    __nv_bfloat16* Ql = Qh + 128 * QP;
    __nv_bfloat16* Kh = Ql + 128 * QP;
    __nv_bfloat16* Kl = Kh + 64 * QP;
    __nv_bfloat16* Vh = Kl + 64 * QP;
    __nv_bfloat16* Vl = Vh + 64 * QP;

    const uint32_t uQh = smem_u32(Qh), uQl = smem_u32(Ql);
    const uint32_t uKh = smem_u32(Kh), uKl = smem_u32(Kl);
    const uint32_t uVh = smem_u32(Vh), uVl = smem_u32(Vl);

    const int tid  = threadIdx.x;
    const int lane = tid & 31;
    const int wid  = tid >> 5;
    const int bh   = blockIdx.y;
    const int m0   = blockIdx.x * 128;

    const size_t pbase = (size_t)bh * SEQ * HD;
    const __nv_bfloat16* pqh = g_qh + pbase;
    const __nv_bfloat16* pql = g_ql + pbase;
    const __nv_bfloat16* pkh = g_kh + pbase;
    const __nv_bfloat16* pkl = g_kl + pbase;
    const __nv_bfloat16* pvh = g_vh + pbase;
    const __nv_bfloat16* pvl = g_vl + pbase;

    /* load Q tile (128 x 64, hi+lo) */
#pragma unroll
    for (int t = 0; t < 8; t++) {
        int idx = t * 256 + tid;        /* 0..2047 */
        int row = idx >> 4;
        int g   = idx & 15;
        size_t go = (size_t)(m0 + row) * HD + g * 4;
        *(uint2*)&Qh[row * QP + g * 4] = *(const uint2*)&pqh[go];
        *(uint2*)&Ql[row * QP + g * 4] = *(const uint2*)&pql[go];
    }

    float o[8][4];
#pragma unroll
    for (int n = 0; n < 8; n++)
#pragma unroll
        for (int r = 0; r < 4; r++) o[n][r] = 0.f;
    float mrow[2] = {-1e30f, -1e30f};
    float lrow[2] = {0.f, 0.f};

    /* ldmatrix lane offsets */
    const int a_row = wid * 16 + (lane & 15);
    const int a_kof = (lane >> 4) * 8;
    const int b_row = (lane & 7) + (lane >> 4) * 8;
    const int b_kof = ((lane >> 3) & 1) * 8;
    const int v_key = ((lane >> 3) & 1) * 8 + (lane & 7);
    const int v_col = (lane >> 4) * 8;

    for (int c = 0; c < 16; c++) {
        const int key0 = c * 64;
        __syncthreads();
#pragma unroll
        for (int t = 0; t < 4; t++) {
            int idx = t * 256 + tid;    /* 0..1023 */
            int row = idx >> 4;
            int g   = idx & 15;
            size_t go = (size_t)(key0 + row) * HD + g * 4;
            uint32_t so = row * QP + g * 4;
            *(uint2*)&Kh[so] = *(const uint2*)&pkh[go];
            *(uint2*)&Kl[so] = *(const uint2*)&pkl[go];
            *(uint2*)&Vh[so] = *(const uint2*)&pvh[go];
            *(uint2*)&Vl[so] = *(const uint2*)&pvl[go];
        }
        __syncthreads();

        /* ---- S = Q K^T over 64-key chunk ---- */
        float s[8][4];
#pragma unroll
        for (int n = 0; n < 8; n++)
#pragma unroll
            for (int r = 0; r < 4; r++) s[n][r] = 0.f;

#pragma unroll
        for (int kk = 0; kk < 4; kk++) {
            uint32_t qhf[4], qlf[4];
            uint32_t aoff = (uint32_t)(a_row * QP + kk * 16 + a_kof) * 2;
            ldm_x4(qhf, uQh + aoff);
            ldm_x4(qlf, uQl + aoff);

            uint32_t kbh[4][4], kbl[4][4];
#pragma unroll
            for (int bi = 0; bi < 4; bi++) {
                uint32_t boff = (uint32_t)((bi * 16 + b_row) * QP + kk * 16 + b_kof) * 2;
                ldm_x4(kbh[bi], uKh + boff);
                ldm_x4(kbl[bi], uKl + boff);
            }
#pragma unroll
            for (int ni = 0; ni < 8; ni++) {
                const uint32_t* bhp = &kbh[ni >> 1][(ni & 1) * 2];
                const uint32_t* blp = &kbl[ni >> 1][(ni & 1) * 2];
                mma_bf16(s[ni], qhf, bhp);
                mma_bf16(s[ni], qhf, blp);
                mma_bf16(s[ni], qlf, bhp);
            }
        }

        /* ---- online softmax (warp-local, quad shuffles) ---- */
        float alpha[2];
#pragma unroll
        for (int r = 0; r < 2; r++) {
            float mx = -1e30f;
#pragma unroll
            for (int ni = 0; ni < 8; ni++)
                mx = fmaxf(mx, fmaxf(s[ni][r * 2], s[ni][r * 2 + 1]));
            mx = fmaxf(mx, __shfl_xor_sync(0xffffffffu, mx, 1));
            mx = fmaxf(mx, __shfl_xor_sync(0xffffffffu, mx, 2));
            float mnew = fmaxf(mrow[r], mx);
            alpha[r] = __expf(mrow[r] - mnew);
            mrow[r] = mnew;
            float ls = 0.f;
#pragma unroll
            for (int ni = 0; ni < 8; ni++) {
                s[ni][r * 2]     = __expf(s[ni][r * 2]     - mnew);
                s[ni][r * 2 + 1] = __expf(s[ni][r * 2 + 1] - mnew);
                ls += s[ni][r * 2] + s[ni][r * 2 + 1];
            }
            ls += __shfl_xor_sync(0xffffffffu, ls, 1);
            ls += __shfl_xor_sync(0xffffffffu, ls, 2);
            lrow[r] = lrow[r] * alpha[r] + ls;
#pragma unroll
            for (int ni = 0; ni < 8; ni++) {
                o[ni][r * 2]     *= alpha[r];
                o[ni][r * 2 + 1] *= alpha[r];
            }
        }

        /* ---- O += P V ---- */
#pragma unroll
        for (int kk = 0; kk < 4; kk++) {
            /* P A-frags from s[2kk], s[2kk+1] (hi/lo split) */
            uint32_t pha[4], pla[4];
#pragma unroll
            for (int q = 0; q < 4; q++) {
                float f0 = (q & 2) ? s[2 * kk + 1][(q & 1) * 2]     : s[2 * kk][(q & 1) * 2];
                float f1 = (q & 2) ? s[2 * kk + 1][(q & 1) * 2 + 1] : s[2 * kk][(q & 1) * 2 + 1];
                __nv_bfloat162 h2 = __floats2bfloat162_rn(f0, f1);
                __nv_bfloat162 l2 = __floats2bfloat162_rn(f0 - __bfloat162float(h2.x),
                                                          f1 - __bfloat162float(h2.y));
                pha[q] = *(uint32_t*)&h2;
                pla[q] = *(uint32_t*)&l2;
            }
            /* NOTE frag order: a0=(row,k0),a1=(row+8,k0),a2=(row,k8),a3=(row+8,k8)
               q mapping above: q0=(row,k0) q1=(row+8,k0) q2=(row,k8) q3=(row+8,k8) ✓ */

            uint32_t vbh[4][4], vbl[4][4];
#pragma unroll
            for (int np = 0; np < 4; np++) {
                uint32_t voff = (uint32_t)((kk * 16 + v_key) * QP + np * 16 + v_col) * 2;
                ldm_x4_t(vbh[np], uVh + voff);
                ldm_x4_t(vbl[np], uVl + voff);
            }
#pragma unroll
            for (int ni = 0; ni < 8; ni++) {
                const uint32_t* bhp = &vbh[ni >> 1][(ni & 1) * 2];
                const uint32_t* blp = &vbl[ni >> 1][(ni & 1) * 2];
                mma_bf16(o[ni], pha, bhp);
                mma_bf16(o[ni], pha, blp);
                mma_bf16(o[ni], pla, bhp);
            }
        }
    }

    /* ---- epilogue: normalize, write [b, n, h*64+d] fp32 ---- */
    const int b = bh >> 4;
    const int h = bh & 15;
#pragma unroll
    for (int r = 0; r < 2; r++) {
        float inv = 1.f / lrow[r];
        int row = m0 + wid * 16 + (lane >> 2) + r * 8;
        size_t base = ((size_t)(b * SEQ + row)) * DIMV + h * HD + (lane & 3) * 2;
#pragma unroll
        for (int ni = 0; ni < 8; ni++)
            *(float2*)&g_attn[base + ni * 8] =
                make_float2(o[ni][r * 2] * inv, o[ni][r * 2 + 1] * inv);
    }
}

/* ------------------------------------------------------------------ */
extern "C" void kernel_launch(void* const* d_in, const int* in_sizes, int n_in,
                              void* d_out, int out_size)
{
    const float* x = nullptr;
    const float* Wqkv = nullptr;
    const float* Wproj = nullptr;
    const float* bproj = nullptr;
    for (int i = 0; i < n_in; i++) {
        switch (in_sizes[i]) {
            case 8388608: x     = (const float*)d_in[i]; break;
            case 3145728: Wqkv  = (const float*)d_in[i]; break;
            case 1048576: Wproj = (const float*)d_in[i]; break;
            case 1024:    bproj = (const float*)d_in[i]; break;
            default: break;
        }
    }
    float* out = (float*)d_out;

    /* QKV GEMM -> bf16 hi/lo planes */
    {
        dim3 grid(3 * DIMV / 128, MTOT / 128);
        gemm_mma<0><<<grid, 256>>>(x, Wqkv, 3 * DIMV, nullptr, nullptr);
    }

    /* tensor-core attention */
    {
        size_t smem = (size_t)(2 * 128 + 4 * 64) * QP * sizeof(__nv_bfloat16); /* 73728 */
        cudaFuncSetAttribute(attn_mma, cudaFuncAttributeMaxDynamicSharedMemorySize,
                             (int)smem);
        dim3 grid(SEQ / 128, BATCH * HEADS);   /* 8 x 128 */
        attn_mma<<<grid, 256, smem>>>();
    }

    /* projection GEMM + bias */
    {
        dim3 grid(DIMV / 128, MTOT / 128);
        gemm_mma<1><<<grid, 256>>>(nullptr, Wproj, DIMV, bproj, out);
    }
    (void)out_size; (void)n_in;
}